// round 2
// baseline (speedup 1.0000x reference)
#include <cuda_runtime.h>

// HCEN forward: out = (mean_S(x) @ W_enc^T + b_enc) @ W_out^T + b_out
// x[16,4096,1024] f32; W[1024,1024] each. HBM-bound on the 256 MB x read.

#define BATCH 16
#define SEQ   4096
#define DIM   1024
#define NCHUNK 64
#define SCHUNK (SEQ / NCHUNK)   // 64
#define KSPLIT 4
#define KCH    (DIM / KSPLIT)   // 256

// Device-global scratch (no allocation allowed).
__device__ float g_partials[NCHUNK * BATCH * DIM];   // 4 MB
__device__ float g_m[BATCH * DIM];                   // 64 KB
__device__ float g_enc[BATCH * DIM];                 // 64 KB
__device__ float g_gpart[KSPLIT * BATCH * DIM];      // 256 KB

// ---------------------------------------------------------------------------
// Pass 1: partial sums over S-chunks. grid (16, 64), block 256.
// Each thread owns one float4 column group and sums 64 rows; fully coalesced.
// ---------------------------------------------------------------------------
__global__ void mean_partial_kernel(const float* __restrict__ x) {
    const int b = blockIdx.x;
    const int c = blockIdx.y;
    const int t = threadIdx.x;

    const float4* __restrict__ x4 =
        reinterpret_cast<const float4*>(x + ((size_t)b * SEQ + (size_t)c * SCHUNK) * DIM);

    float4 acc = make_float4(0.f, 0.f, 0.f, 0.f);
#pragma unroll 16
    for (int s = 0; s < SCHUNK; s++) {
        float4 v = x4[(size_t)s * (DIM / 4) + t];
        acc.x += v.x; acc.y += v.y; acc.z += v.z; acc.w += v.w;
    }
    reinterpret_cast<float4*>(g_partials)[((size_t)c * BATCH + b) * (DIM / 4) + t] = acc;
}

// ---------------------------------------------------------------------------
// Pass 2: reduce 64 chunk partials -> mean. grid 16, block 256.
// ---------------------------------------------------------------------------
__global__ void mean_reduce_kernel() {
    const int b = blockIdx.x;
    const int t = threadIdx.x;

    float4 acc = make_float4(0.f, 0.f, 0.f, 0.f);
#pragma unroll
    for (int c = 0; c < NCHUNK; c++) {
        float4 v = reinterpret_cast<const float4*>(g_partials)[((size_t)c * BATCH + b) * (DIM / 4) + t];
        acc.x += v.x; acc.y += v.y; acc.z += v.z; acc.w += v.w;
    }
    const float inv = 1.0f / (float)SEQ;
    acc.x *= inv; acc.y *= inv; acc.z *= inv; acc.w *= inv;
    reinterpret_cast<float4*>(g_m)[(size_t)b * (DIM / 4) + t] = acc;
}

// ---------------------------------------------------------------------------
// GEMM partial: part[kc][b][h] = dot(A[b][kc*256:+256], W[h][kc*256:+256])
// grid (DIM/8=128, BATCH/8=2, KSPLIT=4) = 1024 blocks, 256 threads (8 warps).
// One warp per h-column; 8-batch A slice staged in 8 KB shared.
// stage 0: A = g_m; stage 1: A = g_enc.
// ---------------------------------------------------------------------------
__global__ void gemm_part_kernel(int stage,
                                 const float* __restrict__ W) {
    __shared__ float4 smA[8 * (KCH / 4)];   // 8 batches x 256 K = 8 KB

    const float* __restrict__ A = (stage == 0) ? g_m : g_enc;

    const int t    = threadIdx.x;
    const int w    = t >> 5;
    const int lane = t & 31;
    const int b0   = blockIdx.y * 8;
    const int kc   = blockIdx.z;
    const int ko4  = kc * (KCH / 4);        // float4 offset of K-slice

    // Stage A slice: 8 batches x 64 float4 = 512 float4, 2 per thread.
    const float4* __restrict__ A4 = reinterpret_cast<const float4*>(A);
#pragma unroll
    for (int i = 0; i < 2; i++) {
        int idx = t + i * 256;              // 0..511
        int bb = idx >> 6;                  // batch within group
        int jj = idx & 63;                  // float4 within slice
        smA[idx] = A4[(size_t)(b0 + bb) * (DIM / 4) + ko4 + jj];
    }
    __syncthreads();

    const int h = blockIdx.x * 8 + w;
    const float4* __restrict__ W4 =
        reinterpret_cast<const float4*>(W + (size_t)h * DIM) + ko4;

    float acc[8];
#pragma unroll
    for (int b = 0; b < 8; b++) acc[b] = 0.f;

#pragma unroll
    for (int it = 0; it < 2; it++) {
        const int j = it * 32 + lane;       // 0..63
        const float4 wv = W4[j];
#pragma unroll
        for (int b = 0; b < 8; b++) {
            const float4 mv = smA[b * 64 + j];
            acc[b] += wv.x * mv.x + wv.y * mv.y + wv.z * mv.z + wv.w * mv.w;
        }
    }

#pragma unroll
    for (int b = 0; b < 8; b++) {
        float v = acc[b];
#pragma unroll
        for (int off = 16; off > 0; off >>= 1)
            v += __shfl_down_sync(0xffffffffu, v, off);
        if (lane == 0)
            g_gpart[((size_t)kc * BATCH + (b0 + b)) * DIM + h] = v;
    }
}

// ---------------------------------------------------------------------------
// Combine: out[b][h] = sum_kc part[kc][b][h] + bias[h]
// grid 64, block 256 — one element per thread.
// stage 0 -> g_enc, stage 1 -> dout.
// ---------------------------------------------------------------------------
__global__ void gemm_combine_kernel(int stage,
                                    const float* __restrict__ bias,
                                    float* __restrict__ dout) {
    float* __restrict__ out = (stage == 0) ? g_enc : dout;

    const int idx = blockIdx.x * 256 + threadIdx.x;   // 0..16383
    const int h = idx & (DIM - 1);

    float v = bias[h];
#pragma unroll
    for (int kc = 0; kc < KSPLIT; kc++)
        v += g_gpart[(size_t)kc * BATCH * DIM + idx];
    out[idx] = v;
}

extern "C" void kernel_launch(void* const* d_in, const int* in_sizes, int n_in,
                              void* d_out, int out_size) {
    const float* x     = (const float*)d_in[0];
    const float* W_enc = (const float*)d_in[1];
    const float* b_enc = (const float*)d_in[2];
    const float* W_out = (const float*)d_in[3];
    const float* b_out = (const float*)d_in[4];
    float* out = (float*)d_out;

    (void)in_sizes; (void)n_in; (void)out_size;

    mean_partial_kernel<<<dim3(BATCH, NCHUNK), 256>>>(x);
    mean_reduce_kernel<<<BATCH, 256>>>();
    gemm_part_kernel<<<dim3(DIM / 8, BATCH / 8, KSPLIT), 256>>>(0, W_enc);
    gemm_combine_kernel<<<BATCH * DIM / 256, 256>>>(0, b_enc, nullptr);
    gemm_part_kernel<<<dim3(DIM / 8, BATCH / 8, KSPLIT), 256>>>(1, W_out);
    gemm_combine_kernel<<<BATCH * DIM / 256, 256>>>(1, b_out, out);
}

// round 3
// speedup vs baseline: 1.0979x; 1.0979x over previous
#include <cuda_runtime.h>

// HCEN forward: out = (mean_S(x) @ W_enc^T + b_enc) @ W_out^T + b_out
// x[16,4096,1024] f32; W[1024,1024] each. HBM-bound on the 256 MB x read.

#define BATCH 16
#define SEQ   4096
#define DIM   1024
#define NCHUNK 64
#define SCHUNK (SEQ / NCHUNK)   // 64
#define KSP    8
#define KCH    (DIM / KSP)      // 128
#define HG     16               // h columns per block
#define NHG    (DIM / HG)       // 64 h-groups

// Device-global scratch (no allocation allowed).
__device__ float g_partials[NCHUNK * BATCH * DIM];   // 4 MB
__device__ float g_m[BATCH * DIM];                   // 64 KB
__device__ float g_enc[BATCH * DIM];                 // 64 KB
__device__ float g_gpart[KSP * BATCH * DIM];         // 512 KB
__device__ unsigned int g_sem[NHG];                  // zero-init; each use resets itself

// ---------------------------------------------------------------------------
// Pass 1: partial sums over S-chunks. grid (16, 64), block 256.
// Fully coalesced; __ldcs streaming (x is read-once, keep out of L2).
// ---------------------------------------------------------------------------
__global__ void __launch_bounds__(256) mean_partial_kernel(const float* __restrict__ x) {
    const int b = blockIdx.x;
    const int c = blockIdx.y;
    const int t = threadIdx.x;

    const float4* __restrict__ x4 =
        reinterpret_cast<const float4*>(x + ((size_t)b * SEQ + (size_t)c * SCHUNK) * DIM);

    float4 acc = make_float4(0.f, 0.f, 0.f, 0.f);
#pragma unroll 16
    for (int s = 0; s < SCHUNK; s++) {
        float4 v = __ldcs(&x4[(size_t)s * (DIM / 4) + t]);
        acc.x += v.x; acc.y += v.y; acc.z += v.z; acc.w += v.w;
    }
    reinterpret_cast<float4*>(g_partials)[((size_t)c * BATCH + b) * (DIM / 4) + t] = acc;
}

// ---------------------------------------------------------------------------
// Pass 2: reduce 64 chunk partials -> mean. grid (16, 4), block 256.
// Each block owns a 64-float4 dim slice of one batch; 4 threads per column
// each sum 16 chunks, then smem-combine. Deterministic fixed order.
// ---------------------------------------------------------------------------
__global__ void __launch_bounds__(256) mean_reduce_kernel() {
    __shared__ float4 red[256];
    const int b   = blockIdx.x;
    const int q   = blockIdx.y;          // dim quarter (64 float4)
    const int t   = threadIdx.x;
    const int col = t & 63;
    const int cg  = t >> 6;              // chunk group 0..3

    const float4* __restrict__ p4 = reinterpret_cast<const float4*>(g_partials);
    float4 acc = make_float4(0.f, 0.f, 0.f, 0.f);
#pragma unroll 16
    for (int i = 0; i < 16; i++) {
        const int c = cg * 16 + i;
        float4 v = p4[((size_t)c * BATCH + b) * (DIM / 4) + q * 64 + col];
        acc.x += v.x; acc.y += v.y; acc.z += v.z; acc.w += v.w;
    }
    red[t] = acc;
    __syncthreads();
    if (t < 64) {
        float4 a = red[t], b1 = red[t + 64], c1 = red[t + 128], d1 = red[t + 192];
        const float inv = 1.0f / (float)SEQ;
        float4 r;
        r.x = (a.x + b1.x + c1.x + d1.x) * inv;
        r.y = (a.y + b1.y + c1.y + d1.y) * inv;
        r.z = (a.z + b1.z + c1.z + d1.z) * inv;
        r.w = (a.w + b1.w + c1.w + d1.w) * inv;
        reinterpret_cast<float4*>(g_m)[(size_t)b * (DIM / 4) + q * 64 + t] = r;
    }
}

// ---------------------------------------------------------------------------
// GEMM with fused K-split combine (threadfence-reduction pattern):
// grid (NHG=64, KSP=8), block 256 (8 warps). Block = 16 h x 16 b x 128 K.
// Warp w handles h columns {hg*16 + 2w, +1}; lane owns 1 float4 of the K
// slice per h. Partials -> g_gpart; the LAST arriving kc block per h-group
// sums all 8 partials in fixed order + bias and writes the final result,
// then resets its semaphore (graph-replay safe). No extra kernels.
// stage 0: A=g_m  -> g_enc ; stage 1: A=g_enc -> dout.
// ---------------------------------------------------------------------------
__global__ void __launch_bounds__(256) gemm_fused_kernel(int stage,
                                                         const float* __restrict__ W,
                                                         const float* __restrict__ bias,
                                                         float* __restrict__ dout) {
    __shared__ float4 smA[BATCH * (KCH / 4)];   // 16 b x 32 f4 = 8 KB
    __shared__ bool isLast;

    const float* __restrict__ A = (stage == 0) ? g_m : g_enc;
    float* __restrict__ out     = (stage == 0) ? g_enc : dout;

    const int t    = threadIdx.x;
    const int w    = t >> 5;
    const int lane = t & 31;
    const int hg   = blockIdx.x;        // 0..63
    const int kc   = blockIdx.y;        // 0..7
    const int ko4  = kc * (KCH / 4);    // float4 offset of K slice

    // Stage A slice: 16 batches x 32 float4 = 512 float4, 2 per thread.
    const float4* __restrict__ A4 = reinterpret_cast<const float4*>(A);
#pragma unroll
    for (int i = 0; i < 2; i++) {
        int idx = t + i * 256;          // 0..511
        int bb = idx >> 5;              // batch
        int jj = idx & 31;              // float4 within slice
        smA[idx] = A4[(size_t)bb * (DIM / 4) + ko4 + jj];
    }
    __syncthreads();

    const int h0 = hg * HG + w * 2;
    const float4 wa = reinterpret_cast<const float4*>(W + (size_t)h0 * DIM)[ko4 + lane];
    const float4 wb = reinterpret_cast<const float4*>(W + (size_t)(h0 + 1) * DIM)[ko4 + lane];

    float acc0[BATCH], acc1[BATCH];
#pragma unroll
    for (int b = 0; b < BATCH; b++) {
        const float4 a = smA[b * 32 + lane];
        acc0[b] = wa.x * a.x + wa.y * a.y + wa.z * a.z + wa.w * a.w;
        acc1[b] = wb.x * a.x + wb.y * a.y + wb.z * a.z + wb.w * a.w;
    }

    // Warp-reduce all 32 accumulators (independent chains -> good ILP).
#pragma unroll
    for (int off = 16; off > 0; off >>= 1) {
#pragma unroll
        for (int b = 0; b < BATCH; b++) {
            acc0[b] += __shfl_down_sync(0xffffffffu, acc0[b], off);
            acc1[b] += __shfl_down_sync(0xffffffffu, acc1[b], off);
        }
    }
    if (lane == 0) {
#pragma unroll
        for (int b = 0; b < BATCH; b++) {
            g_gpart[((size_t)kc * BATCH + b) * DIM + h0]     = acc0[b];
            g_gpart[((size_t)kc * BATCH + b) * DIM + h0 + 1] = acc1[b];
        }
    }

    // Fused combine: last kc block for this h-group does the final sum.
    __threadfence();
    if (t == 0) {
        unsigned int old = atomicAdd(&g_sem[hg], 1u);
        isLast = (old == KSP - 1);
        if (isLast) g_sem[hg] = 0;      // reset for next launch/replay
    }
    __syncthreads();
    if (isLast) {
        // 256 threads, one output each: b = t>>4, h = hg*16 + (t&15)
        const int b = t >> 4;
        const int h = hg * HG + (t & 15);
        float v = bias[h];
#pragma unroll
        for (int k2 = 0; k2 < KSP; k2++)
            v += g_gpart[((size_t)k2 * BATCH + b) * DIM + h];
        out[(size_t)b * DIM + h] = v;
    }
}

extern "C" void kernel_launch(void* const* d_in, const int* in_sizes, int n_in,
                              void* d_out, int out_size) {
    const float* x     = (const float*)d_in[0];
    const float* W_enc = (const float*)d_in[1];
    const float* b_enc = (const float*)d_in[2];
    const float* W_out = (const float*)d_in[3];
    const float* b_out = (const float*)d_in[4];
    float* out = (float*)d_out;

    (void)in_sizes; (void)n_in; (void)out_size;

    mean_partial_kernel<<<dim3(BATCH, NCHUNK), 256>>>(x);
    mean_reduce_kernel<<<dim3(BATCH, 4), 256>>>();
    gemm_fused_kernel<<<dim3(NHG, KSP), 256>>>(0, W_enc, b_enc, nullptr);
    gemm_fused_kernel<<<dim3(NHG, KSP), 256>>>(1, W_out, b_out, out);
}

// round 4
// speedup vs baseline: 1.1506x; 1.0480x over previous
#include <cuda_runtime.h>

// HCEN forward: out = (mean_S(x) @ W_enc^T + b_enc) @ W_out^T + b_out
// x[16,4096,1024] f32; W[1024,1024] each. HBM-bound on the 256 MB x read.

#define BATCH 16
#define SEQ   4096
#define DIM   1024
#define NCHUNK 64
#define SCHUNK (SEQ / NCHUNK)   // 64

// Device-global scratch (no allocation allowed).
__device__ float g_partials[NCHUNK * BATCH * DIM];   // 4 MB
__device__ float g_m[BATCH * DIM];                   // 64 KB
__device__ float g_enc[BATCH * DIM];                 // 64 KB
__device__ float g_sink[1];

// ---------------------------------------------------------------------------
// Pass 1: partial sums over S-chunks. grid (16, 64), block 256.
// Fully coalesced; __ldcs streaming (x is read-once, keep out of L2).
// ---------------------------------------------------------------------------
__global__ void __launch_bounds__(256) mean_partial_kernel(const float* __restrict__ x) {
    const int b = blockIdx.x;
    const int c = blockIdx.y;
    const int t = threadIdx.x;

    const float4* __restrict__ x4 =
        reinterpret_cast<const float4*>(x + ((size_t)b * SEQ + (size_t)c * SCHUNK) * DIM);

    float4 acc = make_float4(0.f, 0.f, 0.f, 0.f);
#pragma unroll 16
    for (int s = 0; s < SCHUNK; s++) {
        float4 v = __ldcs(&x4[(size_t)s * (DIM / 4) + t]);
        acc.x += v.x; acc.y += v.y; acc.z += v.z; acc.w += v.w;
    }
    reinterpret_cast<float4*>(g_partials)[((size_t)c * BATCH + b) * (DIM / 4) + t] = acc;
}

// ---------------------------------------------------------------------------
// Pass 2: blocks 0..63 reduce the 64 chunk partials -> mean.
//         blocks 64..191 stream W_enc / W_out into L2 (__ldcg) so the GEMM
//         kernels hit L2 instead of DRAM (x's 256 MB stream evicted them).
// grid 192, block 256.
// ---------------------------------------------------------------------------
__global__ void __launch_bounds__(256) mean_reduce_kernel(const float* __restrict__ Wenc,
                                                          const float* __restrict__ Wout) {
    const int bid = blockIdx.x;
    const int t   = threadIdx.x;

    if (bid < 64) {
        __shared__ float4 red[256];
        const int b   = bid >> 2;
        const int q   = bid & 3;           // dim quarter (64 float4)
        const int col = t & 63;
        const int cg  = t >> 6;            // chunk group 0..3

        const float4* __restrict__ p4 = reinterpret_cast<const float4*>(g_partials);
        float4 acc = make_float4(0.f, 0.f, 0.f, 0.f);
#pragma unroll 16
        for (int i = 0; i < 16; i++) {
            const int c = cg * 16 + i;
            float4 v = p4[((size_t)c * BATCH + b) * (DIM / 4) + q * 64 + col];
            acc.x += v.x; acc.y += v.y; acc.z += v.z; acc.w += v.w;
        }
        red[t] = acc;
        __syncthreads();
        if (t < 64) {
            float4 a = red[t], b1 = red[t + 64], c1 = red[t + 128], d1 = red[t + 192];
            const float inv = 1.0f / (float)SEQ;
            float4 r;
            r.x = (a.x + b1.x + c1.x + d1.x) * inv;
            r.y = (a.y + b1.y + c1.y + d1.y) * inv;
            r.z = (a.z + b1.z + c1.z + d1.z) * inv;
            r.w = (a.w + b1.w + c1.w + d1.w) * inv;
            reinterpret_cast<float4*>(g_m)[(size_t)b * (DIM / 4) + q * 64 + t] = r;
        }
    } else {
        // L2 prefetch: 128 blocks x 64 KB = 8 MB (both weight matrices).
        const int p = bid - 64;                    // 0..127
        const float4* __restrict__ M4 =
            reinterpret_cast<const float4*>((p < 64) ? Wenc : Wout);
        const size_t base = (size_t)(p & 63) * 4096;   // f4 offset, 64 blocks/matrix
        float s = 0.f;
#pragma unroll 16
        for (int i = 0; i < 16; i++) {
            float4 v = __ldcg(&M4[base + t + i * 256]);
            s += v.x + v.y + v.z + v.w;
        }
        if (s == 1.2345678e38f) g_sink[0] = s;     // never true; keeps loads alive
    }
}

// ---------------------------------------------------------------------------
// GEMM: out[b][h] = dot(A[b], W[h]) + bias[h],  A = [16,1024].
// grid (DIM/4=256, 2), block 256 (8 warps).
// Block = 4 h-columns x 8 batches (one batch-half); warp = 1 h x 4 batches,
// full K=1024 (8 independent float4 W loads per lane -> high MLP, all L2
// hits after prefetch). acc[4] -> 20-shuffle tail, lane0 writes finals.
// stage 0: A=g_m -> g_enc ; stage 1: A=g_enc -> dout.
// ---------------------------------------------------------------------------
__global__ void __launch_bounds__(256) gemm_kernel(int stage,
                                                   const float* __restrict__ W,
                                                   const float* __restrict__ bias,
                                                   float* __restrict__ dout) {
    __shared__ float4 smA[8 * (DIM / 4)];   // 8 batches x 1024 K = 32 KB

    const float* __restrict__ A = (stage == 0) ? g_m : g_enc;
    float* __restrict__ out     = (stage == 0) ? g_enc : dout;

    const int t     = threadIdx.x;
    const int w     = t >> 5;
    const int lane  = t & 31;
    const int hg    = blockIdx.x;          // 0..255 (4 h each)
    const int bhalf = blockIdx.y;          // 0 or 1 (8 batches each)

    // Stage 8 rows of A: 2048 float4, 8 per thread.
    const float4* __restrict__ A4 =
        reinterpret_cast<const float4*>(A) + (size_t)bhalf * 8 * (DIM / 4);
#pragma unroll
    for (int i = 0; i < 8; i++)
        smA[t + i * 256] = A4[t + i * 256];
    __syncthreads();

    const int h  = hg * 4 + (w >> 1);      // warp's h column
    const int br = (w & 1) * 4;            // local batch row 0 or 4

    // 8 independent full-row W loads (L2-resident after prefetch).
    const float4* __restrict__ W4 = reinterpret_cast<const float4*>(W + (size_t)h * DIM);
    float4 wr[8];
#pragma unroll
    for (int i = 0; i < 8; i++)
        wr[i] = W4[lane + i * 32];

    float acc[4] = {0.f, 0.f, 0.f, 0.f};
#pragma unroll
    for (int i = 0; i < 8; i++) {
        const int j = lane + i * 32;
#pragma unroll
        for (int b = 0; b < 4; b++) {
            const float4 a = smA[(br + b) * (DIM / 4) + j];
            acc[b] += wr[i].x * a.x + wr[i].y * a.y + wr[i].z * a.z + wr[i].w * a.w;
        }
    }

#pragma unroll
    for (int off = 16; off > 0; off >>= 1) {
#pragma unroll
        for (int b = 0; b < 4; b++)
            acc[b] += __shfl_down_sync(0xffffffffu, acc[b], off);
    }
    if (lane == 0) {
        const float bv = bias[h];
        const int gb0 = bhalf * 8 + br;
#pragma unroll
        for (int b = 0; b < 4; b++)
            out[(size_t)(gb0 + b) * DIM + h] = acc[b] + bv;
    }
}

extern "C" void kernel_launch(void* const* d_in, const int* in_sizes, int n_in,
                              void* d_out, int out_size) {
    const float* x     = (const float*)d_in[0];
    const float* W_enc = (const float*)d_in[1];
    const float* b_enc = (const float*)d_in[2];
    const float* W_out = (const float*)d_in[3];
    const float* b_out = (const float*)d_in[4];
    float* out = (float*)d_out;

    (void)in_sizes; (void)n_in; (void)out_size;

    mean_partial_kernel<<<dim3(BATCH, NCHUNK), 256>>>(x);
    mean_reduce_kernel<<<192, 256>>>(W_enc, W_out);
    gemm_kernel<<<dim3(DIM / 4, 2), 256>>>(0, W_enc, b_enc, nullptr);
    gemm_kernel<<<dim3(DIM / 4, 2), 256>>>(1, W_out, b_out, out);
}

// round 5
// speedup vs baseline: 1.1782x; 1.0240x over previous
#include <cuda_runtime.h>

// HCEN forward: out = (mean_S(x) @ W_enc^T + b_enc) @ W_out^T + b_out
// x[16,4096,1024] f32. 256 MB x read dominates (~32 us HBM floor).
// Tail (reduce + both GEMMs) fused into one persistent 128-block kernel
// with device-wide barriers (128 blocks <= 148 SMs -> all co-resident).

#define BATCH 16
#define SEQ   4096
#define DIM   1024
#define NCHUNK 64
#define SCHUNK (SEQ / NCHUNK)   // 64
#define FB    128               // fused-kernel grid size

// Device-global scratch (no allocation allowed).
__device__ float g_partials[NCHUNK * BATCH * DIM];   // 4 MB
__device__ float g_m[BATCH * DIM];                   // 64 KB
__device__ float g_enc[BATCH * DIM];                 // 64 KB
__device__ volatile unsigned g_bar[2];               // zero-init, self-resetting
__device__ unsigned g_exit;

// ---------------------------------------------------------------------------
// Pass 1: partial sums over S-chunks. grid (16, 64), block 256.
// Fully coalesced; __ldcs streaming (x is read-once, keep out of L2).
// ---------------------------------------------------------------------------
__global__ void __launch_bounds__(256) mean_partial_kernel(const float* __restrict__ x) {
    const int b = blockIdx.x;
    const int c = blockIdx.y;
    const int t = threadIdx.x;

    const float4* __restrict__ x4 =
        reinterpret_cast<const float4*>(x + ((size_t)b * SEQ + (size_t)c * SCHUNK) * DIM);

    float4 acc = make_float4(0.f, 0.f, 0.f, 0.f);
#pragma unroll 16
    for (int s = 0; s < SCHUNK; s++) {
        float4 v = __ldcs(&x4[(size_t)s * (DIM / 4) + t]);
        acc.x += v.x; acc.y += v.y; acc.z += v.z; acc.w += v.w;
    }
    reinterpret_cast<float4*>(g_partials)[((size_t)c * BATCH + b) * (DIM / 4) + t] = acc;
}

// ---------------------------------------------------------------------------
// Device-wide barrier for the persistent kernel (all FB blocks resident).
// ---------------------------------------------------------------------------
__device__ __forceinline__ void grid_barrier(int which) {
    __syncthreads();
    if (threadIdx.x == 0) {
        __threadfence();
        atomicAdd((unsigned*)&g_bar[which], 1u);
        while (g_bar[which] < FB) { }
        __threadfence();
    }
    __syncthreads();
}

// ---------------------------------------------------------------------------
// Fused tail: reduce -> GEMM1 -> GEMM2. grid FB=128, block 256 (8 warps).
// Block bid owns h rows [bid*8, bid*8+8); warp w owns h = bid*8 + w.
//   (a) W_enc row slice -> 8 float4 registers (latency hidden by reduce)
//   (b) L2-prefetch W_out slice
//   (c) reduce: block (b=bid>>3, q=bid&7) sums 64 chunks for 32 f4 cols
//   barrier -> (d) enc = m @ Wenc^T + benc  (W from registers)
//   barrier -> (e) out = enc @ Wout^T + bout (W from L2)
// Self-resetting barriers/exit counter => graph-replay safe, deterministic.
// ---------------------------------------------------------------------------
__global__ void __launch_bounds__(256) fused_tail_kernel(const float* __restrict__ Wenc,
                                                         const float* __restrict__ benc,
                                                         const float* __restrict__ Wout,
                                                         const float* __restrict__ bout,
                                                         float* __restrict__ dout) {
    __shared__ float4 smA[8 * (DIM / 4)];   // 32 KB: 8 batches x full K
    __shared__ float4 red[256];

    const int t    = threadIdx.x;
    const int w    = t >> 5;
    const int lane = t & 31;
    const int bid  = blockIdx.x;
    const int h    = bid * 8 + w;

    // (a) W_enc rows into registers (independent of everything).
    const float4* __restrict__ We4 = reinterpret_cast<const float4*>(Wenc) + (size_t)h * (DIM / 4);
    float4 wr[8];
#pragma unroll
    for (int i = 0; i < 8; i++)
        wr[i] = We4[lane + i * 32];

    // (b) L2-prefetch this block's W_out slice (8 rows = 32 KB = 256 lines).
    {
        const char* wo = reinterpret_cast<const char*>(Wout) + (size_t)bid * 32768 + (size_t)t * 128;
        asm volatile("prefetch.global.L2 [%0];" :: "l"(wo));
    }

    // (c) reduce partials -> g_m. Block handles batch b, f4 cols [q*32, q*32+32).
    {
        const int b   = bid >> 3;
        const int q   = bid & 7;
        const int col = t & 31;
        const int cg  = t >> 5;    // 8 chunk-groups of 8
        const float4* __restrict__ p4 = reinterpret_cast<const float4*>(g_partials);
        float4 acc = make_float4(0.f, 0.f, 0.f, 0.f);
#pragma unroll
        for (int i = 0; i < 8; i++) {
            const int c = cg * 8 + i;
            float4 v = p4[((size_t)c * BATCH + b) * (DIM / 4) + q * 32 + col];
            acc.x += v.x; acc.y += v.y; acc.z += v.z; acc.w += v.w;
        }
        red[t] = acc;
        __syncthreads();
        if (t < 32) {
            float4 r = make_float4(0.f, 0.f, 0.f, 0.f);
#pragma unroll
            for (int g = 0; g < 8; g++) {
                float4 v = red[t + g * 32];
                r.x += v.x; r.y += v.y; r.z += v.z; r.w += v.w;
            }
            const float inv = 1.0f / (float)SEQ;
            r.x *= inv; r.y *= inv; r.z *= inv; r.w *= inv;
            reinterpret_cast<float4*>(g_m)[(size_t)b * (DIM / 4) + q * 32 + t] = r;
        }
    }

    grid_barrier(0);

    // (d) GEMM1: enc[b][h] = m[b].Wenc[h] + benc[h], W in registers.
    {
        const float4* __restrict__ M4 = reinterpret_cast<const float4*>(g_m);
        const float bv = benc[h];
#pragma unroll
        for (int half = 0; half < 2; half++) {
#pragma unroll
            for (int i = 0; i < 8; i++)
                smA[t + i * 256] = M4[(size_t)half * 2048 + t + i * 256];
            __syncthreads();

            float acc[8] = {0.f, 0.f, 0.f, 0.f, 0.f, 0.f, 0.f, 0.f};
#pragma unroll
            for (int i = 0; i < 8; i++) {
                const int j = lane + i * 32;
#pragma unroll
                for (int b = 0; b < 8; b++) {
                    const float4 a = smA[b * 256 + j];
                    acc[b] += wr[i].x * a.x + wr[i].y * a.y + wr[i].z * a.z + wr[i].w * a.w;
                }
            }
#pragma unroll
            for (int off = 16; off > 0; off >>= 1)
#pragma unroll
                for (int b = 0; b < 8; b++)
                    acc[b] += __shfl_down_sync(0xffffffffu, acc[b], off);
            if (lane == 0) {
#pragma unroll
                for (int b = 0; b < 8; b++)
                    g_enc[(size_t)(half * 8 + b) * DIM + h] = acc[b] + bv;
            }
            __syncthreads();
        }
    }

    grid_barrier(1);

    // (e) GEMM2: out[b][h] = enc[b].Wout[h] + bout[h], W from L2 (prefetched).
    {
        const float4* __restrict__ Wo4 = reinterpret_cast<const float4*>(Wout) + (size_t)h * (DIM / 4);
        float4 wo[8];
#pragma unroll
        for (int i = 0; i < 8; i++)
            wo[i] = Wo4[lane + i * 32];

        const float4* __restrict__ E4 = reinterpret_cast<const float4*>(g_enc);
        const float bv = bout[h];
#pragma unroll
        for (int half = 0; half < 2; half++) {
#pragma unroll
            for (int i = 0; i < 8; i++)
                smA[t + i * 256] = E4[(size_t)half * 2048 + t + i * 256];
            __syncthreads();

            float acc[8] = {0.f, 0.f, 0.f, 0.f, 0.f, 0.f, 0.f, 0.f};
#pragma unroll
            for (int i = 0; i < 8; i++) {
                const int j = lane + i * 32;
#pragma unroll
                for (int b = 0; b < 8; b++) {
                    const float4 a = smA[b * 256 + j];
                    acc[b] += wo[i].x * a.x + wo[i].y * a.y + wo[i].z * a.z + wo[i].w * a.w;
                }
            }
#pragma unroll
            for (int off = 16; off > 0; off >>= 1)
#pragma unroll
                for (int b = 0; b < 8; b++)
                    acc[b] += __shfl_down_sync(0xffffffffu, acc[b], off);
            if (lane == 0) {
#pragma unroll
                for (int b = 0; b < 8; b++)
                    dout[(size_t)(half * 8 + b) * DIM + h] = acc[b] + bv;
            }
            __syncthreads();
        }
    }

    // Reset barriers for the next graph replay (last block out resets all).
    __syncthreads();
    if (t == 0) {
        unsigned old = atomicAdd(&g_exit, 1u);
        if (old == FB - 1) {
            g_bar[0] = 0;
            g_bar[1] = 0;
            __threadfence();
            g_exit = 0;
        }
    }
}

extern "C" void kernel_launch(void* const* d_in, const int* in_sizes, int n_in,
                              void* d_out, int out_size) {
    const float* x     = (const float*)d_in[0];
    const float* W_enc = (const float*)d_in[1];
    const float* b_enc = (const float*)d_in[2];
    const float* W_out = (const float*)d_in[3];
    const float* b_out = (const float*)d_in[4];
    float* out = (float*)d_out;

    (void)in_sizes; (void)n_in; (void)out_size;

    mean_partial_kernel<<<dim3(BATCH, NCHUNK), 256>>>(x);
    fused_tail_kernel<<<FB, 256>>>(W_enc, b_enc, W_out, b_out, out);
}

// round 6
// speedup vs baseline: 1.1829x; 1.0040x over previous
#include <cuda_runtime.h>

// HCEN forward, fully fused single persistent kernel:
//   out = (mean_S(x) @ W_enc^T + b_enc) @ W_out^T + b_out
// x[16,4096,1024] f32 (256 MB read ~32us HBM floor).
// 256 blocks, __launch_bounds__(256,2) => all co-resident (2/SM on 148 SMs),
// so device-wide spin barriers are safe. W is L2-prefetched at kernel start
// and its DRAM fetch overlaps the 36us x stream; the GEMM tail then runs
// entirely from L2/registers/smem.

#define BATCH 16
#define SEQ   4096
#define DIM   1024
#define FB    256               // persistent grid size
#define ROWS_PER_BLK (BATCH * SEQ / FB)   // 256

// Device-global scratch (no allocation allowed).
__device__ float g_part2[FB * DIM];      // 1 MB  (per-block partial sums)
__device__ float g_m[BATCH * DIM];       // 64 KB
__device__ float g_enc[BATCH * DIM];     // 64 KB
__device__ volatile unsigned g_bar[3];   // zero-init; self-resetting
__device__ unsigned g_exit;

__device__ __forceinline__ void grid_barrier(int which) {
    __syncthreads();
    if (threadIdx.x == 0) {
        __threadfence();
        atomicAdd((unsigned*)&g_bar[which], 1u);
        while (g_bar[which] < FB) { }
        __threadfence();
    }
    __syncthreads();
}

__global__ void __launch_bounds__(256, 2)
hcen_fused_kernel(const float* __restrict__ x,
                  const float* __restrict__ Wenc,
                  const float* __restrict__ benc,
                  const float* __restrict__ Wout,
                  const float* __restrict__ bout,
                  float* __restrict__ dout) {
    __shared__ float4 smA[8 * (DIM / 4)];   // 32 KB (A tile; reused as reduce buf)

    const int t    = threadIdx.x;
    const int w    = t >> 5;
    const int lane = t & 31;
    const int bid  = blockIdx.x;

    // ---- (P) L2-prefetch this block's W slices (16 KB of each matrix). ----
    // Issued before the x stream; x uses __ldcs (evict-first) so W stays hot.
    {
        const size_t off = (size_t)bid * 16384 + (size_t)(t & 127) * 128;
        const char* wp = (t < 128) ? reinterpret_cast<const char*>(Wenc) + off
                                   : reinterpret_cast<const char*>(Wout) + off;
        asm volatile("prefetch.global.L2 [%0];" :: "l"(wp));
    }

    // ---- (X) stream x: block sums its 256 contiguous rows of one batch. ----
    {
        const int b  = bid >> 4;           // batch
        const int sc = bid & 15;           // seq chunk
        const float4* __restrict__ x4 =
            reinterpret_cast<const float4*>(x + ((size_t)b * SEQ + (size_t)sc * ROWS_PER_BLK) * DIM);

        float4 acc = make_float4(0.f, 0.f, 0.f, 0.f);
#pragma unroll 16
        for (int s = 0; s < ROWS_PER_BLK; s++) {
            float4 v = __ldcs(&x4[(size_t)s * (DIM / 4) + t]);
            acc.x += v.x; acc.y += v.y; acc.z += v.z; acc.w += v.w;
        }
        reinterpret_cast<float4*>(g_part2)[(size_t)bid * (DIM / 4) + t] = acc;
    }

    grid_barrier(0);

    // ---- (R) reduce 16 block-partials per batch -> mean. Blocks 0..127. ----
    if (bid < 128) {
        const int b   = bid >> 3;          // batch
        const int q   = bid & 7;           // 32-f4 column group
        const int col = t & 31;
        const int pg  = t >> 5;            // 8 groups x 2 partials
        const float4* __restrict__ p4 = reinterpret_cast<const float4*>(g_part2);

        float4 acc = make_float4(0.f, 0.f, 0.f, 0.f);
#pragma unroll
        for (int i = 0; i < 2; i++) {
            const int p = pg * 2 + i;      // partial 0..15
            float4 v = p4[(size_t)(b * 16 + p) * (DIM / 4) + q * 32 + col];
            acc.x += v.x; acc.y += v.y; acc.z += v.z; acc.w += v.w;
        }
        smA[t] = acc;
        __syncthreads();
        if (t < 32) {
            float4 r = make_float4(0.f, 0.f, 0.f, 0.f);
#pragma unroll
            for (int g = 0; g < 8; g++) {
                float4 v = smA[t + g * 32];
                r.x += v.x; r.y += v.y; r.z += v.z; r.w += v.w;
            }
            const float inv = 1.0f / (float)SEQ;
            r.x *= inv; r.y *= inv; r.z *= inv; r.w *= inv;
            reinterpret_cast<float4*>(g_m)[(size_t)b * (DIM / 4) + q * 32 + t] = r;
        }
    }

    grid_barrier(1);

    // ---- (G1) enc = m @ Wenc^T + benc.  Warp = 1 h x 8 batches. ----
    // h = (bid>>1)*8 + w; half = bid&1 selects batches [half*8, half*8+8).
    const int h    = (bid >> 1) * 8 + w;
    const int half = bid & 1;
    {
        const float4* __restrict__ M4 = reinterpret_cast<const float4*>(g_m);
#pragma unroll
        for (int i = 0; i < 8; i++)
            smA[t + i * 256] = M4[(size_t)half * 2048 + t + i * 256];
        __syncthreads();

        const float4* __restrict__ W4 = reinterpret_cast<const float4*>(Wenc) + (size_t)h * (DIM / 4);
        float4 wr[8];
#pragma unroll
        for (int i = 0; i < 8; i++)
            wr[i] = W4[lane + i * 32];

        float acc[8] = {0.f, 0.f, 0.f, 0.f, 0.f, 0.f, 0.f, 0.f};
#pragma unroll
        for (int i = 0; i < 8; i++) {
            const int j = lane + i * 32;
#pragma unroll
            for (int b = 0; b < 8; b++) {
                const float4 a = smA[b * 256 + j];
                acc[b] += wr[i].x * a.x + wr[i].y * a.y + wr[i].z * a.z + wr[i].w * a.w;
            }
        }
#pragma unroll
        for (int off = 16; off > 0; off >>= 1)
#pragma unroll
            for (int b = 0; b < 8; b++)
                acc[b] += __shfl_down_sync(0xffffffffu, acc[b], off);
        if (lane == 0) {
            const float bv = benc[h];
#pragma unroll
            for (int b = 0; b < 8; b++)
                g_enc[(size_t)(half * 8 + b) * DIM + h] = acc[b] + bv;
        }
    }

    grid_barrier(2);

    // ---- (G2) out = enc @ Wout^T + bout.  Same decomposition. ----
    {
        const float4* __restrict__ E4 = reinterpret_cast<const float4*>(g_enc);
#pragma unroll
        for (int i = 0; i < 8; i++)
            smA[t + i * 256] = E4[(size_t)half * 2048 + t + i * 256];
        __syncthreads();

        const float4* __restrict__ W4 = reinterpret_cast<const float4*>(Wout) + (size_t)h * (DIM / 4);
        float4 wr[8];
#pragma unroll
        for (int i = 0; i < 8; i++)
            wr[i] = W4[lane + i * 32];

        float acc[8] = {0.f, 0.f, 0.f, 0.f, 0.f, 0.f, 0.f, 0.f};
#pragma unroll
        for (int i = 0; i < 8; i++) {
            const int j = lane + i * 32;
#pragma unroll
            for (int b = 0; b < 8; b++) {
                const float4 a = smA[b * 256 + j];
                acc[b] += wr[i].x * a.x + wr[i].y * a.y + wr[i].z * a.z + wr[i].w * a.w;
            }
        }
#pragma unroll
        for (int off = 16; off > 0; off >>= 1)
#pragma unroll
            for (int b = 0; b < 8; b++)
                acc[b] += __shfl_down_sync(0xffffffffu, acc[b], off);
        if (lane == 0) {
            const float bv = bout[h];
#pragma unroll
            for (int b = 0; b < 8; b++)
                dout[(size_t)(half * 8 + b) * DIM + h] = acc[b] + bv;
        }
    }

    // ---- reset barriers for next graph replay (last block out). ----
    __syncthreads();
    if (t == 0) {
        unsigned old = atomicAdd(&g_exit, 1u);
        if (old == FB - 1) {
            g_bar[0] = 0;
            g_bar[1] = 0;
            g_bar[2] = 0;
            __threadfence();
            g_exit = 0;
        }
    }
}

extern "C" void kernel_launch(void* const* d_in, const int* in_sizes, int n_in,
                              void* d_out, int out_size) {
    const float* x     = (const float*)d_in[0];
    const float* W_enc = (const float*)d_in[1];
    const float* b_enc = (const float*)d_in[2];
    const float* W_out = (const float*)d_in[3];
    const float* b_out = (const float*)d_in[4];
    float* out = (float*)d_out;

    (void)in_sizes; (void)n_in; (void)out_size;

    hcen_fused_kernel<<<FB, 256>>>(x, W_enc, b_enc, W_out, b_out, out);
}